// round 16
// baseline (speedup 1.0000x reference)
#include <cuda_runtime.h>
#include <cuda_fp16.h>
#include <cstdint>

// ---------------------------------------------------------------------------
// CausalSelfAttention, all matmuls mma.sync fp16 1-pass, fp32 accum.
// Error budget ~5.1e-4 vs 1e-3 gate.
//   GEMM: CTA 128x256, BK=64, 512 threads, 3-stage ring (distance-2 prefetch,
//         single barrier/iter), 1 CTA/SM. Warp grid 4x4, warp tile 32x64.
//   Attention: BM=64, BN=64, 4 blocks/SM, QK^T and P@V 1-pass (unchanged).
// ---------------------------------------------------------------------------

#define T_SEQ   2048
#define NEMB    1024
#define KDIM    1024

// ---------------- scratch ---------------------------------------------------
__device__ __half g_qkvhi[8192 * 3072];
__device__ __half g_xhi[8192 * 1024];
__device__ __half g_yhi[8192 * 1024];
__device__ __half g_wahi[3072 * 1024];
__device__ __half g_wphi[1024 * 1024];

// ---------------- PTX helpers ----------------------------------------------
__device__ __forceinline__ uint32_t smem_u32(const void* p) {
    uint32_t a;
    asm("{ .reg .u64 t; cvta.to.shared.u64 t, %1; cvt.u32.u64 %0, t; }"
        : "=r"(a) : "l"(p));
    return a;
}
__device__ __forceinline__ void cp_async16(uint32_t dst, const void* src) {
    asm volatile("cp.async.cg.shared.global [%0], [%1], 16;" :: "r"(dst), "l"(src));
}
__device__ __forceinline__ void cp_commit() {
    asm volatile("cp.async.commit_group;" ::: "memory");
}
template <int N>
__device__ __forceinline__ void cp_wait() {
    asm volatile("cp.async.wait_group %0;" :: "n"(N) : "memory");
}
__device__ __forceinline__ void ldmatrix_x4(uint32_t* r, uint32_t addr) {
    asm volatile("ldmatrix.sync.aligned.m8n8.x4.shared.b16 {%0,%1,%2,%3}, [%4];"
                 : "=r"(r[0]), "=r"(r[1]), "=r"(r[2]), "=r"(r[3]) : "r"(addr));
}
__device__ __forceinline__ void ldmatrix_x4_t(uint32_t* r, uint32_t addr) {
    asm volatile("ldmatrix.sync.aligned.m8n8.x4.trans.shared.b16 {%0,%1,%2,%3}, [%4];"
                 : "=r"(r[0]), "=r"(r[1]), "=r"(r[2]), "=r"(r[3]) : "r"(addr));
}
__device__ __forceinline__ void mma_f16(float* d, const uint32_t* a, const uint32_t* b) {
    asm volatile(
        "mma.sync.aligned.m16n8k16.row.col.f32.f16.f16.f32 "
        "{%0,%1,%2,%3}, {%4,%5,%6,%7}, {%8,%9}, {%0,%1,%2,%3};"
        : "+f"(d[0]), "+f"(d[1]), "+f"(d[2]), "+f"(d[3])
        : "r"(a[0]), "r"(a[1]), "r"(a[2]), "r"(a[3]), "r"(b[0]), "r"(b[1]));
}

// ---------------------------------------------------------------------------
// 1-pass fp16 GEMM: C[M,N] = A[M,K] @ B[N,K]^T.
// CTA 128x256, BK=64, 512 threads, 3-stage ring / distance-2 prefetch /
// single barrier per iteration, 1 CTA/SM.
// Warp grid 4x4 (wm 4 rows x wn 4 cols), warp tile 32x64.
// SPLIT: 0 -> fp32 C, 2 -> fp16 C.
// ---------------------------------------------------------------------------
#define G_LDS    144
#define OFF_A    0
#define OFF_B    18432                   // A: 128 rows * 144
#define G_STAGE  55296                   // + B: 256 rows * 144
#define GEMM_SMEM (3 * G_STAGE)          // 165888 B

__device__ __forceinline__ void gemm_load_stage(
    uint32_t sb,
    const __half* __restrict__ A, const __half* __restrict__ B,
    int bm, int bn, int k0, int tid)
{
#pragma unroll
    for (int i = 0; i < 2; i++) {        // A: 128 rows x 8 chunks = 1024
        int idx = tid + i * 512;
        int r = idx >> 3, c = idx & 7;
        uint32_t off = (uint32_t)(r * G_LDS + c * 16);
        cp_async16(sb + OFF_A + off, A + (size_t)(bm + r) * KDIM + k0 + c * 8);
    }
#pragma unroll
    for (int i = 0; i < 4; i++) {        // B: 256 rows x 8 chunks = 2048
        int idx = tid + i * 512;
        int r = idx >> 3, c = idx & 7;
        uint32_t off = (uint32_t)(r * G_LDS + c * 16);
        cp_async16(sb + OFF_B + off, B + (size_t)(bn + r) * KDIM + k0 + c * 8);
    }
    cp_commit();
}

template <int SPLIT>
__global__ void __launch_bounds__(512, 1) gemm_mma_kernel(
    const __half* __restrict__ A, const __half* __restrict__ B,
    float* __restrict__ Cf, __half* __restrict__ Ch, int N)
{
    extern __shared__ char smem[];
    const uint32_t sbase = smem_u32(smem);

    const int tid  = threadIdx.x;
    const int lane = tid & 31;
    const int wid  = tid >> 5;           // 0..15
    const int bm   = blockIdx.y * 128;
    const int bn   = blockIdx.x * 256;
    const int wm   = (wid & 3) * 32;     // 4 warp rows
    const int wn   = (wid >> 2) * 64;    // 4 warp cols

    float acc[2][8][4];
#pragma unroll
    for (int mi = 0; mi < 2; mi++)
#pragma unroll
        for (int ni = 0; ni < 8; ni++)
#pragma unroll
            for (int q = 0; q < 4; q++) acc[mi][ni][q] = 0.0f;

    const uint32_t lm_off = (uint32_t)((lane & 15) * G_LDS + (lane >> 4) * 16);

    const int nk = KDIM / 64;            // 16
    gemm_load_stage(sbase + 0 * G_STAGE, A, B, bm, bn, 0,  tid);
    gemm_load_stage(sbase + 1 * G_STAGE, A, B, bm, bn, 64, tid);

    for (int it = 0; it < nk; it++) {
        const uint32_t sb = sbase + (uint32_t)(it % 3) * G_STAGE;

        if (it < nk - 2) cp_wait<1>(); else cp_wait<0>();
        __syncthreads();   // (a) stage 'it' visible; (b) readers of stage
                           // (it+2)%3 (== it-1) finished before overwrite.

        if (it + 2 < nk)
            gemm_load_stage(sbase + (uint32_t)((it + 2) % 3) * G_STAGE,
                            A, B, bm, bn, (it + 2) * 64, tid);

#pragma unroll
        for (int ks = 0; ks < 4; ks++) {
            const uint32_t kcol = (uint32_t)(ks * 32);

            uint32_t bf[8][2];
#pragma unroll
            for (int pair = 0; pair < 4; pair++) {
                uint32_t r4[4];
                ldmatrix_x4(r4, sb + OFF_B +
                            (uint32_t)((wn + pair * 16) * G_LDS) + kcol + lm_off);
                bf[pair * 2 + 0][0] = r4[0]; bf[pair * 2 + 1][0] = r4[1];
                bf[pair * 2 + 0][1] = r4[2]; bf[pair * 2 + 1][1] = r4[3];
            }

            uint32_t af[2][4];
#pragma unroll
            for (int mi = 0; mi < 2; mi++)
                ldmatrix_x4(af[mi], sb + OFF_A +
                            (uint32_t)((wm + mi * 16) * G_LDS) + kcol + lm_off);

#pragma unroll
            for (int mi = 0; mi < 2; mi++)
#pragma unroll
                for (int ni = 0; ni < 8; ni++) mma_f16(acc[mi][ni], af[mi], bf[ni]);
        }
    }

    const int row_base = bm + wm + (lane >> 2);
    const int col_base = bn + wn + (lane & 3) * 2;
#pragma unroll
    for (int mi = 0; mi < 2; mi++) {
#pragma unroll
        for (int ni = 0; ni < 8; ni++) {
            int cc = col_base + ni * 8;
#pragma unroll
            for (int half = 0; half < 2; half++) {
                int r = row_base + mi * 16 + half * 8;
                float v0 = acc[mi][ni][half * 2 + 0];
                float v1 = acc[mi][ni][half * 2 + 1];
                if (SPLIT == 0) {
                    *(float2*)&Cf[(size_t)r * N + cc] = make_float2(v0, v1);
                } else {
                    *(__half2*)&Ch[(size_t)r * N + cc] = __floats2half2_rn(v0, v1);
                }
            }
        }
    }
}

// ---------------------------------------------------------------------------
// conversions
// ---------------------------------------------------------------------------
__global__ void __launch_bounds__(256) cvt_kernel(const float* __restrict__ in,
                                                  __half* __restrict__ hi, int n4)
{
    int i = blockIdx.x * 256 + threadIdx.x;
    if (i >= n4) return;
    float4 v = ((const float4*)in)[i];
    ((__half2*)hi)[i * 2 + 0] = __floats2half2_rn(v.x, v.y);
    ((__half2*)hi)[i * 2 + 1] = __floats2half2_rn(v.z, v.w);
}

__global__ void __launch_bounds__(256) t_hi_kernel(const float* __restrict__ in,
                                                   __half* __restrict__ hi,
                                                   int K, int N)
{
    __shared__ float t[32][33];
    const int tx = threadIdx.x, ty = threadIdx.y;
    const int x  = blockIdx.x * 32 + tx;
    const int y0 = blockIdx.y * 32;
#pragma unroll
    for (int j = 0; j < 32; j += 8)
        t[ty + j][tx] = in[(size_t)(y0 + ty + j) * N + x];
    __syncthreads();
#pragma unroll
    for (int j = 0; j < 32; j += 8) {
        float v = t[tx][ty + j];
        int nIdx = blockIdx.x * 32 + ty + j;
        int kIdx = y0 + tx;
        hi[(size_t)nIdx * K + kIdx] = __float2half(v);
    }
}

// ---------------------------------------------------------------------------
// Tensor-core flash attention, causal. 128 threads (4 warps), BM=64, BN=64.
// QK^T 1-pass, P@V 1-pass. 2-stage KV pipeline, 4 blocks/SM. (unchanged)
// ---------------------------------------------------------------------------
#define A_LDS   144
#define AQ_REG  9216
#define AQ_HI   0
#define A_ST0   AQ_REG
#define A_KHI   0
#define A_VHI   AQ_REG
#define A_STAGE (2 * AQ_REG)
#define ATTN_SMEM (AQ_REG + 2 * A_STAGE)   // 46080 B

__device__ __forceinline__ void attn_load_kv(
    uint32_t sb, const __half* __restrict__ qhi, int tglob0, int h, int tid)
{
#pragma unroll
    for (int j = 0; j < 4; j++) {
        int idx = tid + j * 128;
        int r = idx >> 3, c = idx & 7;
        size_t g = (size_t)(tglob0 + r) * 3072 + h * 64 + c * 8;
        uint32_t off = (uint32_t)(r * A_LDS + c * 16);
        cp_async16(sb + A_KHI + off, qhi + g + 1024);
        cp_async16(sb + A_VHI + off, qhi + g + 2048);
    }
    cp_commit();
}

__global__ void __launch_bounds__(128, 4) attn_kernel(
    const __half* __restrict__ qkvhi, __half* __restrict__ yhi)
{
    extern __shared__ char smem[];
    const uint32_t sbase = smem_u32(smem);

    const int qb = (int)gridDim.x - 1 - (int)blockIdx.x;
    const int bh = blockIdx.y;
    const int b  = bh >> 4;
    const int h  = bh & 15;

    const int tid  = threadIdx.x;
    const int lane = tid & 31;
    const int w    = tid >> 5;
    const int r0   = lane >> 2;
    const int c2   = (lane & 3) * 2;

    const uint32_t lm_off = (uint32_t)((lane & 15) * A_LDS + (lane >> 4) * 16);
    const int q_tok0 = b * T_SEQ + qb * 64;

    {
#pragma unroll
        for (int j = 0; j < 4; j++) {
            int idx = tid + j * 128;
            int r = idx >> 3, c = idx & 7;
            size_t g = (size_t)(q_tok0 + r) * 3072 + h * 64 + c * 8;
            uint32_t off = (uint32_t)(r * A_LDS + c * 16);
            cp_async16(sbase + AQ_HI + off, qkvhi + g);
        }
        attn_load_kv(sbase + A_ST0, qkvhi, b * T_SEQ, h, tid);
    }
    const int ktiles = qb + 1;
    if (ktiles > 1)
        attn_load_kv(sbase + A_ST0 + A_STAGE, qkvhi, b * T_SEQ + 64, h, tid);

    uint32_t qfhi[4][4];
    float oacc[8][4];
    float m_i[2] = {-1e30f, -1e30f};
    float l_i[2] = {0.0f, 0.0f};
#pragma unroll
    for (int dt = 0; dt < 8; dt++)
#pragma unroll
        for (int q = 0; q < 4; q++) oacc[dt][q] = 0.0f;

    for (int kt = 0; kt < ktiles; kt++) {
        const uint32_t sb = sbase + A_ST0 + (uint32_t)(kt & 1) * A_STAGE;

        if (kt < ktiles - 1) cp_wait<1>(); else cp_wait<0>();
        __syncthreads();

        if (kt == 0) {
#pragma unroll
            for (int kk = 0; kk < 4; kk++) {
                uint32_t addr = (uint32_t)(w * 16 * A_LDS + kk * 32) + lm_off;
                ldmatrix_x4(qfhi[kk], sbase + AQ_HI + addr);
            }
        }

        float sacc[8][4];
#pragma unroll
        for (int nt = 0; nt < 8; nt++)
#pragma unroll
            for (int q = 0; q < 4; q++) sacc[nt][q] = 0.0f;

#pragma unroll
        for (int kk = 0; kk < 4; kk++) {
            const uint32_t kcol = (uint32_t)(kk * 32);
#pragma unroll
            for (int pair = 0; pair < 4; pair++) {
                uint32_t rh[4];
                uint32_t addr = (uint32_t)(pair * 16 * A_LDS) + kcol + lm_off;
                ldmatrix_x4(rh, sb + A_KHI + addr);
                uint32_t b0[2] = {rh[0], rh[2]}, b1[2] = {rh[1], rh[3]};
                mma_f16(sacc[pair * 2 + 0], qfhi[kk], b0);
                mma_f16(sacc[pair * 2 + 1], qfhi[kk], b1);
            }
        }

#pragma unroll
        for (int nt = 0; nt < 8; nt++)
#pragma unroll
            for (int q = 0; q < 4; q++) sacc[nt][q] *= 0.03125f;

        if (kt == qb) {
            const int rowl0 = w * 16 + r0;
#pragma unroll
            for (int nt = 0; nt < 8; nt++) {
                int col0 = nt * 8 + c2;
                if (col0 > rowl0)         sacc[nt][0] = -1e30f;
                if (col0 + 1 > rowl0)     sacc[nt][1] = -1e30f;
                if (col0 > rowl0 + 8)     sacc[nt][2] = -1e30f;
                if (col0 + 1 > rowl0 + 8) sacc[nt][3] = -1e30f;
            }
        }

        float mn[2] = {-1e30f, -1e30f};
#pragma unroll
        for (int nt = 0; nt < 8; nt++) {
            mn[0] = fmaxf(mn[0], fmaxf(sacc[nt][0], sacc[nt][1]));
            mn[1] = fmaxf(mn[1], fmaxf(sacc[nt][2], sacc[nt][3]));
        }
#pragma unroll
        for (int o = 1; o < 4; o <<= 1) {
            mn[0] = fmaxf(mn[0], __shfl_xor_sync(0xffffffffu, mn[0], o));
            mn[1] = fmaxf(mn[1], __shfl_xor_sync(0xffffffffu, mn[1], o));
        }
        float alpha[2];
#pragma unroll
        for (int q = 0; q < 2; q++) {
            float mNew = fmaxf(m_i[q], mn[q]);
            alpha[q] = __expf(m_i[q] - mNew);
            m_i[q] = mNew;
        }
        float rs[2] = {0.0f, 0.0f};
#pragma unroll
        for (int nt = 0; nt < 8; nt++) {
            sacc[nt][0] = __expf(sacc[nt][0] - m_i[0]);
            sacc[nt][1] = __expf(sacc[nt][1] - m_i[0]);
            sacc[nt][2] = __expf(sacc[nt][2] - m_i[1]);
            sacc[nt][3] = __expf(sacc[nt][3] - m_i[1]);
            rs[0] += sacc[nt][0] + sacc[nt][1];
            rs[1] += sacc[nt][2] + sacc[nt][3];
        }
#pragma unroll
        for (int o = 1; o < 4; o <<= 1) {
            rs[0] += __shfl_xor_sync(0xffffffffu, rs[0], o);
            rs[1] += __shfl_xor_sync(0xffffffffu, rs[1], o);
        }
        l_i[0] = l_i[0] * alpha[0] + rs[0];
        l_i[1] = l_i[1] * alpha[1] + rs[1];
#pragma unroll
        for (int dt = 0; dt < 8; dt++) {
            oacc[dt][0] *= alpha[0]; oacc[dt][1] *= alpha[0];
            oacc[dt][2] *= alpha[1]; oacc[dt][3] *= alpha[1];
        }

#pragma unroll
        for (int kkp = 0; kkp < 4; kkp++) {
            uint32_t phi[4];
#pragma unroll
            for (int half = 0; half < 2; half++) {
                const float* s0 = sacc[2 * kkp + half];
                __half2 h0 = __floats2half2_rn(s0[0], s0[1]);
                __half2 h1 = __floats2half2_rn(s0[2], s0[3]);
                phi[half * 2 + 0] = *(uint32_t*)&h0;
                phi[half * 2 + 1] = *(uint32_t*)&h1;
            }
            const uint32_t krow = (uint32_t)(kkp * 16 * A_LDS);
#pragma unroll
            for (int dp = 0; dp < 4; dp++) {
                uint32_t rh[4];
                uint32_t addr = krow + (uint32_t)(dp * 32) + lm_off;
                ldmatrix_x4_t(rh, sb + A_VHI + addr);
                uint32_t b0[2] = {rh[0], rh[1]}, b1[2] = {rh[2], rh[3]};
                mma_f16(oacc[dp * 2 + 0], phi, b0);
                mma_f16(oacc[dp * 2 + 1], phi, b1);
            }
        }
        __syncthreads();

        if (kt + 2 < ktiles)
            attn_load_kv(sb, qkvhi, b * T_SEQ + (kt + 2) * 64, h, tid);
    }

    float inv0 = 1.0f / l_i[0];
    float inv1 = 1.0f / l_i[1];
    const int tok0 = q_tok0 + w * 16 + r0;
#pragma unroll
    for (int dt = 0; dt < 8; dt++) {
        int col = h * 64 + dt * 8 + c2;
#pragma unroll
        for (int half = 0; half < 2; half++) {
            float inv = half ? inv1 : inv0;
            float v0 = oacc[dt][half * 2 + 0] * inv;
            float v1 = oacc[dt][half * 2 + 1] * inv;
            size_t base = (size_t)(tok0 + half * 8) * NEMB + col;
            *(__half2*)&yhi[base] = __floats2half2_rn(v0, v1);
        }
    }
}

// ---------------------------------------------------------------------------

extern "C" void kernel_launch(void* const* d_in, const int* in_sizes, int n_in,
                              void* d_out, int out_size)
{
    const float* x      = (const float*)d_in[0];
    const float* w_attn = (const float*)d_in[1];
    const float* w_proj = (const float*)d_in[2];
    float* out = (float*)d_out;

    void *qh_p, *xhi_p, *yhi_p, *wahi_p, *wphi_p;
    cudaGetSymbolAddress(&qh_p,   g_qkvhi);
    cudaGetSymbolAddress(&xhi_p,  g_xhi);
    cudaGetSymbolAddress(&yhi_p,  g_yhi);
    cudaGetSymbolAddress(&wahi_p, g_wahi);
    cudaGetSymbolAddress(&wphi_p, g_wphi);

    __half* qkvhi = (__half*)qh_p;
    __half* xhi   = (__half*)xhi_p;
    __half* yhi   = (__half*)yhi_p;
    __half* wahi  = (__half*)wahi_p;
    __half* wphi  = (__half*)wphi_p;

    cudaFuncSetAttribute(gemm_mma_kernel<0>,
                         cudaFuncAttributeMaxDynamicSharedMemorySize, GEMM_SMEM);
    cudaFuncSetAttribute(gemm_mma_kernel<2>,
                         cudaFuncAttributeMaxDynamicSharedMemorySize, GEMM_SMEM);
    cudaFuncSetAttribute(attn_kernel,
                         cudaFuncAttributeMaxDynamicSharedMemorySize, ATTN_SMEM);

    cvt_kernel<<<(8192 * 1024 / 4 + 255) / 256, 256>>>(x, xhi, 8192 * 1024 / 4);
    t_hi_kernel<<<dim3(3072 / 32, 1024 / 32), dim3(32, 8)>>>(w_attn, wahi, 1024, 3072);
    t_hi_kernel<<<dim3(1024 / 32, 1024 / 32), dim3(32, 8)>>>(w_proj, wphi, 1024, 1024);

    // 1) qkv (fp16) = x @ w_attn
    gemm_mma_kernel<2><<<dim3(3072 / 256, 8192 / 128), 512, GEMM_SMEM>>>(
        xhi, wahi, nullptr, qkvhi, 3072);

    // 2) y (fp16) = causal attention
    attn_kernel<<<dim3(32, 64), 128, ATTN_SMEM>>>(qkvhi, yhi);

    // 3) out (fp32) = y @ w_proj
    gemm_mma_kernel<0><<<dim3(1024 / 256, 8192 / 128), 512, GEMM_SMEM>>>(
        yhi, wphi, out, nullptr, 1024);
}

// round 17
// speedup vs baseline: 1.0594x; 1.0594x over previous
#include <cuda_runtime.h>
#include <cuda_fp16.h>
#include <cstdint>

// ---------------------------------------------------------------------------
// CausalSelfAttention, all matmuls mma.sync fp16 1-pass, fp32 accum.
// Error budget ~5.1e-4 vs 1e-3 gate. Best-known config (R14) + fused prologue:
//   GEMM: CTA 128x128, BK=64, 256 thr, 3-stage pipeline, 2 CTAs/SM.
//   Attention: BM=64, BN=64, 4 blocks/SM, QK^T and P@V 1-pass.
//   Conversions: single fused kernel (cvt x + transpose w_attn + w_proj).
// ---------------------------------------------------------------------------

#define T_SEQ   2048
#define NEMB    1024
#define KDIM    1024

// ---------------- scratch ---------------------------------------------------
__device__ __half g_qkvhi[8192 * 3072];
__device__ __half g_xhi[8192 * 1024];
__device__ __half g_yhi[8192 * 1024];
__device__ __half g_wahi[3072 * 1024];
__device__ __half g_wphi[1024 * 1024];

// ---------------- PTX helpers ----------------------------------------------
__device__ __forceinline__ uint32_t smem_u32(const void* p) {
    uint32_t a;
    asm("{ .reg .u64 t; cvta.to.shared.u64 t, %1; cvt.u32.u64 %0, t; }"
        : "=r"(a) : "l"(p));
    return a;
}
__device__ __forceinline__ void cp_async16(uint32_t dst, const void* src) {
    asm volatile("cp.async.cg.shared.global [%0], [%1], 16;" :: "r"(dst), "l"(src));
}
__device__ __forceinline__ void cp_commit() {
    asm volatile("cp.async.commit_group;" ::: "memory");
}
template <int N>
__device__ __forceinline__ void cp_wait() {
    asm volatile("cp.async.wait_group %0;" :: "n"(N) : "memory");
}
__device__ __forceinline__ void ldmatrix_x4(uint32_t* r, uint32_t addr) {
    asm volatile("ldmatrix.sync.aligned.m8n8.x4.shared.b16 {%0,%1,%2,%3}, [%4];"
                 : "=r"(r[0]), "=r"(r[1]), "=r"(r[2]), "=r"(r[3]) : "r"(addr));
}
__device__ __forceinline__ void ldmatrix_x4_t(uint32_t* r, uint32_t addr) {
    asm volatile("ldmatrix.sync.aligned.m8n8.x4.trans.shared.b16 {%0,%1,%2,%3}, [%4];"
                 : "=r"(r[0]), "=r"(r[1]), "=r"(r[2]), "=r"(r[3]) : "r"(addr));
}
__device__ __forceinline__ void mma_f16(float* d, const uint32_t* a, const uint32_t* b) {
    asm volatile(
        "mma.sync.aligned.m16n8k16.row.col.f32.f16.f16.f32 "
        "{%0,%1,%2,%3}, {%4,%5,%6,%7}, {%8,%9}, {%0,%1,%2,%3};"
        : "+f"(d[0]), "+f"(d[1]), "+f"(d[2]), "+f"(d[3])
        : "r"(a[0]), "r"(a[1]), "r"(a[2]), "r"(a[3]), "r"(b[0]), "r"(b[1]));
}

// ---------------------------------------------------------------------------
// 1-pass fp16 GEMM: C[M,N] = A[M,K] @ B[N,K]^T.  (R13/R14 best-known config)
// CTA 128x128, BK=64, 256 threads, 3-stage pipeline, 2 CTAs/SM.
// Warp grid 4x2: warp tile 32x64. SPLIT: 0 -> fp32 C, 2 -> fp16 C.
// ---------------------------------------------------------------------------
#define G_LDS    144
#define OFF_A    0
#define OFF_B    18432
#define G_STAGE  36864
#define GEMM_SMEM (3 * G_STAGE)          // 110592 B

__device__ __forceinline__ void gemm_load_stage(
    uint32_t sb,
    const __half* __restrict__ A, const __half* __restrict__ B,
    int bm, int bn, int k0, int tid)
{
#pragma unroll
    for (int i = 0; i < 4; i++) {
        int idx = tid + i * 256;
        int r = idx >> 3, c = idx & 7;
        uint32_t off = (uint32_t)(r * G_LDS + c * 16);
        cp_async16(sb + OFF_A + off, A + (size_t)(bm + r) * KDIM + k0 + c * 8);
        cp_async16(sb + OFF_B + off, B + (size_t)(bn + r) * KDIM + k0 + c * 8);
    }
    cp_commit();
}

template <int SPLIT>
__global__ void __launch_bounds__(256, 2) gemm_mma_kernel(
    const __half* __restrict__ A, const __half* __restrict__ B,
    float* __restrict__ Cf, __half* __restrict__ Ch, int N)
{
    extern __shared__ char smem[];
    const uint32_t sbase = smem_u32(smem);

    const int tid  = threadIdx.x;
    const int lane = tid & 31;
    const int wid  = tid >> 5;
    const int bm   = blockIdx.y * 128;
    const int bn   = blockIdx.x * 128;
    const int wm   = (wid & 3) * 32;
    const int wn   = (wid >> 2) * 64;

    float acc[2][8][4];
#pragma unroll
    for (int mi = 0; mi < 2; mi++)
#pragma unroll
        for (int ni = 0; ni < 8; ni++)
#pragma unroll
            for (int q = 0; q < 4; q++) acc[mi][ni][q] = 0.0f;

    const uint32_t lm_off = (uint32_t)((lane & 15) * G_LDS + (lane >> 4) * 16);

    const int nk = KDIM / 64;
    gemm_load_stage(sbase + 0 * G_STAGE, A, B, bm, bn, 0,   tid);
    gemm_load_stage(sbase + 1 * G_STAGE, A, B, bm, bn, 64,  tid);
    gemm_load_stage(sbase + 2 * G_STAGE, A, B, bm, bn, 128, tid);

    for (int it = 0; it < nk; it++) {
        const uint32_t sb = sbase + (uint32_t)(it % 3) * G_STAGE;

        if (it < nk - 3) cp_wait<2>();
        else if (it == nk - 3) cp_wait<1>();
        else cp_wait<0>();
        __syncthreads();

#pragma unroll
        for (int ks = 0; ks < 4; ks++) {
            const uint32_t kcol = (uint32_t)(ks * 32);

            uint32_t bf[8][2];
#pragma unroll
            for (int pair = 0; pair < 4; pair++) {
                uint32_t r4[4];
                ldmatrix_x4(r4, sb + OFF_B +
                            (uint32_t)((wn + pair * 16) * G_LDS) + kcol + lm_off);
                bf[pair * 2 + 0][0] = r4[0]; bf[pair * 2 + 1][0] = r4[1];
                bf[pair * 2 + 0][1] = r4[2]; bf[pair * 2 + 1][1] = r4[3];
            }

            uint32_t af[2][4];
#pragma unroll
            for (int mi = 0; mi < 2; mi++)
                ldmatrix_x4(af[mi], sb + OFF_A +
                            (uint32_t)((wm + mi * 16) * G_LDS) + kcol + lm_off);

#pragma unroll
            for (int mi = 0; mi < 2; mi++)
#pragma unroll
                for (int ni = 0; ni < 8; ni++) mma_f16(acc[mi][ni], af[mi], bf[ni]);
        }
        __syncthreads();

        if (it + 3 < nk)
            gemm_load_stage(sbase + (uint32_t)((it + 3) % 3) * G_STAGE,
                            A, B, bm, bn, (it + 3) * 64, tid);
    }

    const int row_base = bm + wm + (lane >> 2);
    const int col_base = bn + wn + (lane & 3) * 2;
#pragma unroll
    for (int mi = 0; mi < 2; mi++) {
#pragma unroll
        for (int ni = 0; ni < 8; ni++) {
            int cc = col_base + ni * 8;
#pragma unroll
            for (int half = 0; half < 2; half++) {
                int r = row_base + mi * 16 + half * 8;
                float v0 = acc[mi][ni][half * 2 + 0];
                float v1 = acc[mi][ni][half * 2 + 1];
                if (SPLIT == 0) {
                    *(float2*)&Cf[(size_t)r * N + cc] = make_float2(v0, v1);
                } else {
                    *(__half2*)&Ch[(size_t)r * N + cc] = __floats2half2_rn(v0, v1);
                }
            }
        }
    }
}

// ---------------------------------------------------------------------------
// fused prologue: region 0 = cvt x (2048 blocks), region 1 = transpose w_attn
// (96x32 = 3072 tiles... dims (3072/32)x(1024/32) = 96x32 = 3072 blocks),
// region 2 = transpose w_proj (32x32 = 1024 blocks). One launch.
// Block layout: 256 threads = (32,8) for transpose regions, flat for cvt.
// ---------------------------------------------------------------------------
#define CVT_BLOCKS  8192                 // 8192*1024/4 elems / 256 thr / 1
#define TA_BX       (3072 / 32)          // 96
#define TA_BLOCKS   (TA_BX * (1024 / 32))    // 3072
#define TP_BX       (1024 / 32)          // 32
#define TP_BLOCKS   (TP_BX * (1024 / 32))    // 1024
#define PRO_BLOCKS  (CVT_BLOCKS + TA_BLOCKS + TP_BLOCKS)

__device__ __forceinline__ void t_hi_tile(const float* __restrict__ in,
                                          __half* __restrict__ hi,
                                          int K, int N, int bxx, int byy)
{
    __shared__ float t[32][33];
    const int tx = threadIdx.x & 31, ty = threadIdx.x >> 5;
    const int x  = bxx * 32 + tx;
    const int y0 = byy * 32;
#pragma unroll
    for (int j = 0; j < 32; j += 8)
        t[ty + j][tx] = in[(size_t)(y0 + ty + j) * N + x];
    __syncthreads();
#pragma unroll
    for (int j = 0; j < 32; j += 8) {
        float v = t[tx][ty + j];
        int nIdx = bxx * 32 + ty + j;
        int kIdx = y0 + tx;
        hi[(size_t)nIdx * K + kIdx] = __float2half(v);
    }
}

__global__ void __launch_bounds__(256) prologue_kernel(
    const float* __restrict__ x,      __half* __restrict__ xhi,
    const float* __restrict__ w_attn, __half* __restrict__ wahi,
    const float* __restrict__ w_proj, __half* __restrict__ wphi)
{
    int blk = blockIdx.x;
    if (blk < CVT_BLOCKS) {
        int i = blk * 256 + threadIdx.x;          // n4 = 8192*1024/4 = CVT_BLOCKS*256
        float4 v = ((const float4*)x)[i];
        ((__half2*)xhi)[i * 2 + 0] = __floats2half2_rn(v.x, v.y);
        ((__half2*)xhi)[i * 2 + 1] = __floats2half2_rn(v.z, v.w);
    } else if (blk < CVT_BLOCKS + TA_BLOCKS) {
        int t = blk - CVT_BLOCKS;
        t_hi_tile(w_attn, wahi, 1024, 3072, t % TA_BX, t / TA_BX);
    } else {
        int t = blk - CVT_BLOCKS - TA_BLOCKS;
        t_hi_tile(w_proj, wphi, 1024, 1024, t % TP_BX, t / TP_BX);
    }
}

// ---------------------------------------------------------------------------
// Tensor-core flash attention, causal. 128 threads (4 warps), BM=64, BN=64.
// QK^T 1-pass, P@V 1-pass. 2-stage KV pipeline, 4 blocks/SM. (R14 config)
// ---------------------------------------------------------------------------
#define A_LDS   144
#define AQ_REG  9216
#define AQ_HI   0
#define A_ST0   AQ_REG
#define A_KHI   0
#define A_VHI   AQ_REG
#define A_STAGE (2 * AQ_REG)
#define ATTN_SMEM (AQ_REG + 2 * A_STAGE)   // 46080 B

__device__ __forceinline__ void attn_load_kv(
    uint32_t sb, const __half* __restrict__ qhi, int tglob0, int h, int tid)
{
#pragma unroll
    for (int j = 0; j < 4; j++) {
        int idx = tid + j * 128;
        int r = idx >> 3, c = idx & 7;
        size_t g = (size_t)(tglob0 + r) * 3072 + h * 64 + c * 8;
        uint32_t off = (uint32_t)(r * A_LDS + c * 16);
        cp_async16(sb + A_KHI + off, qhi + g + 1024);
        cp_async16(sb + A_VHI + off, qhi + g + 2048);
    }
    cp_commit();
}

__global__ void __launch_bounds__(128, 4) attn_kernel(
    const __half* __restrict__ qkvhi, __half* __restrict__ yhi)
{
    extern __shared__ char smem[];
    const uint32_t sbase = smem_u32(smem);

    const int qb = (int)gridDim.x - 1 - (int)blockIdx.x;
    const int bh = blockIdx.y;
    const int b  = bh >> 4;
    const int h  = bh & 15;

    const int tid  = threadIdx.x;
    const int lane = tid & 31;
    const int w    = tid >> 5;
    const int r0   = lane >> 2;
    const int c2   = (lane & 3) * 2;

    const uint32_t lm_off = (uint32_t)((lane & 15) * A_LDS + (lane >> 4) * 16);
    const int q_tok0 = b * T_SEQ + qb * 64;

    {
#pragma unroll
        for (int j = 0; j < 4; j++) {
            int idx = tid + j * 128;
            int r = idx >> 3, c = idx & 7;
            size_t g = (size_t)(q_tok0 + r) * 3072 + h * 64 + c * 8;
            uint32_t off = (uint32_t)(r * A_LDS + c * 16);
            cp_async16(sbase + AQ_HI + off, qkvhi + g);
        }
        attn_load_kv(sbase + A_ST0, qkvhi, b * T_SEQ, h, tid);
    }
    const int ktiles = qb + 1;
    if (ktiles > 1)
        attn_load_kv(sbase + A_ST0 + A_STAGE, qkvhi, b * T_SEQ + 64, h, tid);

    uint32_t qfhi[4][4];
    float oacc[8][4];
    float m_i[2] = {-1e30f, -1e30f};
    float l_i[2] = {0.0f, 0.0f};
#pragma unroll
    for (int dt = 0; dt < 8; dt++)
#pragma unroll
        for (int q = 0; q < 4; q++) oacc[dt][q] = 0.0f;

    for (int kt = 0; kt < ktiles; kt++) {
        const uint32_t sb = sbase + A_ST0 + (uint32_t)(kt & 1) * A_STAGE;

        if (kt < ktiles - 1) cp_wait<1>(); else cp_wait<0>();
        __syncthreads();

        if (kt == 0) {
#pragma unroll
            for (int kk = 0; kk < 4; kk++) {
                uint32_t addr = (uint32_t)(w * 16 * A_LDS + kk * 32) + lm_off;
                ldmatrix_x4(qfhi[kk], sbase + AQ_HI + addr);
            }
        }

        float sacc[8][4];
#pragma unroll
        for (int nt = 0; nt < 8; nt++)
#pragma unroll
            for (int q = 0; q < 4; q++) sacc[nt][q] = 0.0f;

#pragma unroll
        for (int kk = 0; kk < 4; kk++) {
            const uint32_t kcol = (uint32_t)(kk * 32);
#pragma unroll
            for (int pair = 0; pair < 4; pair++) {
                uint32_t rh[4];
                uint32_t addr = (uint32_t)(pair * 16 * A_LDS) + kcol + lm_off;
                ldmatrix_x4(rh, sb + A_KHI + addr);
                uint32_t b0[2] = {rh[0], rh[2]}, b1[2] = {rh[1], rh[3]};
                mma_f16(sacc[pair * 2 + 0], qfhi[kk], b0);
                mma_f16(sacc[pair * 2 + 1], qfhi[kk], b1);
            }
        }

#pragma unroll
        for (int nt = 0; nt < 8; nt++)
#pragma unroll
            for (int q = 0; q < 4; q++) sacc[nt][q] *= 0.03125f;

        if (kt == qb) {
            const int rowl0 = w * 16 + r0;
#pragma unroll
            for (int nt = 0; nt < 8; nt++) {
                int col0 = nt * 8 + c2;
                if (col0 > rowl0)         sacc[nt][0] = -1e30f;
                if (col0 + 1 > rowl0)     sacc[nt][1] = -1e30f;
                if (col0 > rowl0 + 8)     sacc[nt][2] = -1e30f;
                if (col0 + 1 > rowl0 + 8) sacc[nt][3] = -1e30f;
            }
        }

        float mn[2] = {-1e30f, -1e30f};
#pragma unroll
        for (int nt = 0; nt < 8; nt++) {
            mn[0] = fmaxf(mn[0], fmaxf(sacc[nt][0], sacc[nt][1]));
            mn[1] = fmaxf(mn[1], fmaxf(sacc[nt][2], sacc[nt][3]));
        }
#pragma unroll
        for (int o = 1; o < 4; o <<= 1) {
            mn[0] = fmaxf(mn[0], __shfl_xor_sync(0xffffffffu, mn[0], o));
            mn[1] = fmaxf(mn[1], __shfl_xor_sync(0xffffffffu, mn[1], o));
        }
        float alpha[2];
#pragma unroll
        for (int q = 0; q < 2; q++) {
            float mNew = fmaxf(m_i[q], mn[q]);
            alpha[q] = __expf(m_i[q] - mNew);
            m_i[q] = mNew;
        }
        float rs[2] = {0.0f, 0.0f};
#pragma unroll
        for (int nt = 0; nt < 8; nt++) {
            sacc[nt][0] = __expf(sacc[nt][0] - m_i[0]);
            sacc[nt][1] = __expf(sacc[nt][1] - m_i[0]);
            sacc[nt][2] = __expf(sacc[nt][2] - m_i[1]);
            sacc[nt][3] = __expf(sacc[nt][3] - m_i[1]);
            rs[0] += sacc[nt][0] + sacc[nt][1];
            rs[1] += sacc[nt][2] + sacc[nt][3];
        }
#pragma unroll
        for (int o = 1; o < 4; o <<= 1) {
            rs[0] += __shfl_xor_sync(0xffffffffu, rs[0], o);
            rs[1] += __shfl_xor_sync(0xffffffffu, rs[1], o);
        }
        l_i[0] = l_i[0] * alpha[0] + rs[0];
        l_i[1] = l_i[1] * alpha[1] + rs[1];
#pragma unroll
        for (int dt = 0; dt < 8; dt++) {
            oacc[dt][0] *= alpha[0]; oacc[dt][1] *= alpha[0];
            oacc[dt][2] *= alpha[1]; oacc[dt][3] *= alpha[1];
        }

#pragma unroll
        for (int kkp = 0; kkp < 4; kkp++) {
            uint32_t phi[4];
#pragma unroll
            for (int half = 0; half < 2; half++) {
                const float* s0 = sacc[2 * kkp + half];
                __half2 h0 = __floats2half2_rn(s0[0], s0[1]);
                __half2 h1 = __floats2half2_rn(s0[2], s0[3]);
                phi[half * 2 + 0] = *(uint32_t*)&h0;
                phi[half * 2 + 1] = *(uint32_t*)&h1;
            }
            const uint32_t krow = (uint32_t)(kkp * 16 * A_LDS);
#pragma unroll
            for (int dp = 0; dp < 4; dp++) {
                uint32_t rh[4];
                uint32_t addr = krow + (uint32_t)(dp * 32) + lm_off;
                ldmatrix_x4_t(rh, sb + A_VHI + addr);
                uint32_t b0[2] = {rh[0], rh[1]}, b1[2] = {rh[2], rh[3]};
                mma_f16(oacc[dp * 2 + 0], phi, b0);
                mma_f16(oacc[dp * 2 + 1], phi, b1);
            }
        }
        __syncthreads();

        if (kt + 2 < ktiles)
            attn_load_kv(sb, qkvhi, b * T_SEQ + (kt + 2) * 64, h, tid);
    }

    float inv0 = 1.0f / l_i[0];
    float inv1 = 1.0f / l_i[1];
    const int tok0 = q_tok0 + w * 16 + r0;
#pragma unroll
    for (int dt = 0; dt < 8; dt++) {
        int col = h * 64 + dt * 8 + c2;
#pragma unroll
        for (int half = 0; half < 2; half++) {
            float inv = half ? inv1 : inv0;
            float v0 = oacc[dt][half * 2 + 0] * inv;
            float v1 = oacc[dt][half * 2 + 1] * inv;
            size_t base = (size_t)(tok0 + half * 8) * NEMB + col;
            *(__half2*)&yhi[base] = __floats2half2_rn(v0, v1);
        }
    }
}

// ---------------------------------------------------------------------------

extern "C" void kernel_launch(void* const* d_in, const int* in_sizes, int n_in,
                              void* d_out, int out_size)
{
    const float* x      = (const float*)d_in[0];
    const float* w_attn = (const float*)d_in[1];
    const float* w_proj = (const float*)d_in[2];
    float* out = (float*)d_out;

    void *qh_p, *xhi_p, *yhi_p, *wahi_p, *wphi_p;
    cudaGetSymbolAddress(&qh_p,   g_qkvhi);
    cudaGetSymbolAddress(&xhi_p,  g_xhi);
    cudaGetSymbolAddress(&yhi_p,  g_yhi);
    cudaGetSymbolAddress(&wahi_p, g_wahi);
    cudaGetSymbolAddress(&wphi_p, g_wphi);

    __half* qkvhi = (__half*)qh_p;
    __half* xhi   = (__half*)xhi_p;
    __half* yhi   = (__half*)yhi_p;
    __half* wahi  = (__half*)wahi_p;
    __half* wphi  = (__half*)wphi_p;

    cudaFuncSetAttribute(gemm_mma_kernel<0>,
                         cudaFuncAttributeMaxDynamicSharedMemorySize, GEMM_SMEM);
    cudaFuncSetAttribute(gemm_mma_kernel<2>,
                         cudaFuncAttributeMaxDynamicSharedMemorySize, GEMM_SMEM);
    cudaFuncSetAttribute(attn_kernel,
                         cudaFuncAttributeMaxDynamicSharedMemorySize, ATTN_SMEM);

    // 0) fused conversions: x -> fp16, w_attn/w_proj -> transposed fp16
    prologue_kernel<<<PRO_BLOCKS, 256>>>(x, xhi, w_attn, wahi, w_proj, wphi);

    // 1) qkv (fp16) = x @ w_attn
    gemm_mma_kernel<2><<<dim3(3072 / 128, 8192 / 128), 256, GEMM_SMEM>>>(
        xhi, wahi, nullptr, qkvhi, 3072);

    // 2) y (fp16) = causal attention
    attn_kernel<<<dim3(32, 64), 128, ATTN_SMEM>>>(qkvhi, yhi);

    // 3) out (fp32) = y @ w_proj
    gemm_mma_kernel<0><<<dim3(1024 / 128, 8192 / 128), 256, GEMM_SMEM>>>(
        yhi, wphi, out, nullptr, 1024);
}